// round 1
// baseline (speedup 1.0000x reference)
#include <cuda_runtime.h>
#include <math.h>

#define N_IN   512
#define N_OUT  10
#define D_OUT  16
#define D_IN   8
#define NJD    (N_OUT * D_OUT)   // 160 (j,d) pairs
#define NBLK   128
#define N_PER_BLK (N_IN / NBLK)  // 4
#define EPS    1e-7f

// Scratch: per-block partial sums for each (j,d). Overwritten every call,
// never needs zeroing (no atomics). 128*160*4B = 80 KB.
__device__ float g_partials[NBLK * NJD];

// Kernel 1: each block reduces N_PER_BLK n-values for all 160 (j,d) pairs.
// Thread jd reads W[n, j, d, 0..7] as two float4 (32B contiguous per thread,
// coalesced across the 160 threads), dots with x[n, 0..7].
__global__ __launch_bounds__(NJD) void digitcaps_reduce(
    const float* __restrict__ x,   // (512, 8)
    const float* __restrict__ W)   // (1, 512, 10, 16, 8) contiguous
{
    const int jd  = threadIdx.x;            // 0..159
    const int blk = blockIdx.x;             // 0..127

    float acc = 0.0f;
#pragma unroll
    for (int i = 0; i < N_PER_BLK; ++i) {
        const int n = blk * N_PER_BLK + i;
        const float4* xv = reinterpret_cast<const float4*>(x + (size_t)n * D_IN);
        const float4  x0 = xv[0];
        const float4  x1 = xv[1];
        const float4* wv = reinterpret_cast<const float4*>(
            W + (size_t)n * (NJD * D_IN) + (size_t)jd * D_IN);
        const float4  w0 = wv[0];
        const float4  w1 = wv[1];
        acc += w0.x * x0.x + w0.y * x0.y + w0.z * x0.z + w0.w * x0.w;
        acc += w1.x * x1.x + w1.y * x1.y + w1.z * x1.z + w1.w * x1.w;
    }
    g_partials[blk * NJD + jd] = acc;
}

// Kernel 2: final reduction over blocks + elementwise squash.
// Reference squash sums over a size-1 axis, so it is purely elementwise:
//   sq = s*s;  v = (sq/(1+sq)) * (s / (sqrt(sq+EPS)+EPS))
__global__ __launch_bounds__(NJD) void digitcaps_finalize(float* __restrict__ out)
{
    const int jd = threadIdx.x;   // 0..159
    float s = 0.0f;
#pragma unroll 8
    for (int b = 0; b < NBLK; ++b) {
        s += g_partials[b * NJD + jd];
    }
    s *= (1.0f / (float)N_IN);

    const float sq   = s * s;
    const float norm = s / (sqrtf(sq + EPS) + EPS);
    out[jd] = (sq / (1.0f + sq)) * norm;
}

extern "C" void kernel_launch(void* const* d_in, const int* in_sizes, int n_in,
                              void* d_out, int out_size)
{
    // Inputs per setup_inputs order: x (512*8=4096), W (655360).
    // Defensive: identify by element count.
    const float* x;
    const float* W;
    if (in_sizes[0] == N_IN * D_IN) {
        x = (const float*)d_in[0];
        W = (const float*)d_in[1];
    } else {
        x = (const float*)d_in[1];
        W = (const float*)d_in[0];
    }
    float* out = (float*)d_out;  // 160 floats: (1,1,10,16,1)

    digitcaps_reduce<<<NBLK, NJD>>>(x, W);
    digitcaps_finalize<<<1, NJD>>>(out);
}

// round 2
// speedup vs baseline: 1.2647x; 1.2647x over previous
#include <cuda_runtime.h>
#include <math.h>

#define N_IN   512
#define N_OUT  10
#define D_OUT  16
#define D_IN   8
#define NJD    (N_OUT * D_OUT)     // 160 (j,d) pairs
#define NBLK   32
#define SLICES 4
#define NTHR   (NJD * SLICES)      // 640 threads/block
#define N_PER_SLICE 4              // each slice handles 4 n
#define N_PER_BLK   (SLICES * N_PER_SLICE)  // 16 n per block; 32*16 = 512
#define EPS    1e-7f

// Per-block partials, overwritten every call (no zeroing needed).
__device__ float g_partials[NBLK * NJD];   // 20 KB
__device__ unsigned int g_counter;          // zero-initialized at load; reset by last block

__global__ __launch_bounds__(NTHR) void digitcaps_fused(
    const float* __restrict__ x,   // (512, 8)
    const float* __restrict__ W,   // (1, 512, 10, 16, 8) contiguous
    float* __restrict__ out)       // 160 floats
{
    __shared__ float s_part[SLICES * NJD];
    __shared__ bool  s_last;

    const int tid   = threadIdx.x;
    const int jd    = tid % NJD;      // 0..159
    const int slice = tid / NJD;      // 0..3
    const int blk   = blockIdx.x;     // 0..31

    // --- phase 1: per-thread dot over N_PER_SLICE n-rows ---
    float acc = 0.0f;
#pragma unroll
    for (int i = 0; i < N_PER_SLICE; ++i) {
        const int n = blk * N_PER_BLK + slice * N_PER_SLICE + i;
        const float4* xv = reinterpret_cast<const float4*>(x + (size_t)n * D_IN);
        const float4  x0 = xv[0];
        const float4  x1 = xv[1];
        const float4* wv = reinterpret_cast<const float4*>(
            W + (size_t)n * (NJD * D_IN) + (size_t)jd * D_IN);
        const float4  w0 = wv[0];
        const float4  w1 = wv[1];
        acc += w0.x * x0.x + w0.y * x0.y + w0.z * x0.z + w0.w * x0.w;
        acc += w1.x * x1.x + w1.y * x1.y + w1.z * x1.z + w1.w * x1.w;
    }
    s_part[slice * NJD + jd] = acc;
    __syncthreads();

    // --- phase 2: intra-block reduce (slice 0 lanes) + publish partial ---
    if (slice == 0) {
        float bsum = s_part[jd] + s_part[NJD + jd]
                   + s_part[2 * NJD + jd] + s_part[3 * NJD + jd];
        g_partials[blk * NJD + jd] = bsum;
    }
    __threadfence();
    __syncthreads();

    if (tid == 0) {
        unsigned int prev = atomicAdd(&g_counter, 1u);
        s_last = (prev == NBLK - 1);
    }
    __syncthreads();

    if (!s_last) return;

    // --- phase 3: last block sums all partials + squash ---
    __threadfence();  // make all blocks' g_partials writes visible
    if (tid < NJD) {
        float s = 0.0f;
#pragma unroll
        for (int b = 0; b < NBLK; ++b) {
            s += g_partials[b * NJD + tid];
        }
        s *= (1.0f / (float)N_IN);

        const float sq   = s * s;
        const float norm = s / (sqrtf(sq + EPS) + EPS);
        out[tid] = (sq / (1.0f + sq)) * norm;
    }
    if (tid == 0) g_counter = 0u;   // reset for next graph replay
}

extern "C" void kernel_launch(void* const* d_in, const int* in_sizes, int n_in,
                              void* d_out, int out_size)
{
    const float* x;
    const float* W;
    if (in_sizes[0] == N_IN * D_IN) {
        x = (const float*)d_in[0];
        W = (const float*)d_in[1];
    } else {
        x = (const float*)d_in[1];
        W = (const float*)d_in[0];
    }
    float* out = (float*)d_out;

    digitcaps_fused<<<NBLK, NTHR>>>(x, W, out);
}

// round 3
// speedup vs baseline: 1.5426x; 1.2197x over previous
#include <cuda_runtime.h>
#include <math.h>

#define N_IN   512
#define N_OUT  10
#define D_OUT  16
#define D_IN   8
#define NJD    (N_OUT * D_OUT)   // 160 output elements -> 160 blocks
#define NTHR   64                // 2 warps per block
#define N_PER_WARP 256           // each warp reduces 256 n-rows
#define EPS    1e-7f

// One block per (j,d). Each lane owns (pair = lane>>1, half = lane&1):
// iterates n = warp*256 + pair + 16*i, loading W[n, jd, half*4 .. half*4+3]
// and x[n, half*4 .. half*4+3] as float4. 16 fully-unrolled iterations
// => 32 outstanding LDG.128 per lane, DRAM latency amortized by MLP.
__global__ __launch_bounds__(NTHR) void digitcaps_per_jd(
    const float* __restrict__ x,   // (512, 8)
    const float* __restrict__ W,   // (512, 160, 8) contiguous
    float* __restrict__ out)       // 160 floats
{
    __shared__ float s_warp[2];

    const int jd   = blockIdx.x;          // 0..159
    const int warp = threadIdx.x >> 5;    // 0..1
    const int lane = threadIdx.x & 31;
    const int pair = lane >> 1;           // 0..15
    const int half = lane & 1;            // 0..1

    const int n0 = warp * N_PER_WARP + pair;

    float acc = 0.0f;
#pragma unroll
    for (int i = 0; i < 16; ++i) {
        const int n = n0 + i * 16;
        const float4 w4 = *reinterpret_cast<const float4*>(
            W + ((size_t)n * NJD + jd) * D_IN + half * 4);
        const float4 x4 = *reinterpret_cast<const float4*>(
            x + (size_t)n * D_IN + half * 4);
        acc += w4.x * x4.x + w4.y * x4.y + w4.z * x4.z + w4.w * x4.w;
    }

    // warp butterfly reduce
#pragma unroll
    for (int off = 16; off > 0; off >>= 1)
        acc += __shfl_xor_sync(0xFFFFFFFFu, acc, off);

    if (lane == 0) s_warp[warp] = acc;
    __syncthreads();

    if (threadIdx.x == 0) {
        float s = (s_warp[0] + s_warp[1]) * (1.0f / (float)N_IN);
        const float sq   = s * s;
        const float norm = s / (sqrtf(sq + EPS) + EPS);
        out[jd] = (sq / (1.0f + sq)) * norm;
    }
}

extern "C" void kernel_launch(void* const* d_in, const int* in_sizes, int n_in,
                              void* d_out, int out_size)
{
    const float* x;
    const float* W;
    if (in_sizes[0] == N_IN * D_IN) {
        x = (const float*)d_in[0];
        W = (const float*)d_in[1];
    } else {
        x = (const float*)d_in[1];
        W = (const float*)d_in[0];
    }
    float* out = (float*)d_out;

    digitcaps_per_jd<<<NJD, NTHR>>>(x, W, out);
}

// round 4
// speedup vs baseline: 1.6538x; 1.0721x over previous
#include <cuda_runtime.h>
#include <math.h>

#define N_IN   512
#define N_OUT  10
#define D_OUT  16
#define D_IN   8
#define NJD    (N_OUT * D_OUT)   // 160 output elements -> 160 blocks
#define NWARP  8
#define NTHR   (NWARP * 32)      // 256 threads
#define N_PER_WARP (N_IN / NWARP) // 64 n-rows per warp
#define EPS    1e-7f

// One block per (j,d), 8 warps. Lane mapping within a warp:
//   pair = lane>>1 (0..15) selects n-row offset, half = lane&1 selects k-half.
// Warp w covers n in [w*64, (w+1)*64), striding 16 rows per iteration:
// 4 iterations * (1 W float4 + 1 x float4) = 8 LDG.128 per lane, all
// independent -> single L2-latency exposure.
__global__ __launch_bounds__(NTHR) void digitcaps_per_jd(
    const float* __restrict__ x,   // (512, 8)
    const float* __restrict__ W,   // (512, 160, 8) contiguous
    float* __restrict__ out)       // 160 floats
{
    __shared__ float s_warp[NWARP];

    const int jd   = blockIdx.x;          // 0..159
    const int warp = threadIdx.x >> 5;    // 0..7
    const int lane = threadIdx.x & 31;
    const int pair = lane >> 1;           // 0..15
    const int half = lane & 1;            // 0..1

    const int n0 = warp * N_PER_WARP + pair;

    // Batch all 8 loads up front (independent addresses), then FMA.
    float4 w4[4], x4[4];
#pragma unroll
    for (int i = 0; i < 4; ++i) {
        const int n = n0 + i * 16;
        w4[i] = *reinterpret_cast<const float4*>(
            W + ((size_t)n * NJD + jd) * D_IN + half * 4);
        x4[i] = *reinterpret_cast<const float4*>(
            x + (size_t)n * D_IN + half * 4);
    }

    float acc = 0.0f;
#pragma unroll
    for (int i = 0; i < 4; ++i) {
        acc = fmaf(w4[i].x, x4[i].x, acc);
        acc = fmaf(w4[i].y, x4[i].y, acc);
        acc = fmaf(w4[i].z, x4[i].z, acc);
        acc = fmaf(w4[i].w, x4[i].w, acc);
    }

    // warp butterfly reduce
#pragma unroll
    for (int off = 16; off > 0; off >>= 1)
        acc += __shfl_xor_sync(0xFFFFFFFFu, acc, off);

    if (lane == 0) s_warp[warp] = acc;
    __syncthreads();

    if (threadIdx.x == 0) {
        float s = 0.0f;
#pragma unroll
        for (int w = 0; w < NWARP; ++w) s += s_warp[w];
        s *= (1.0f / (float)N_IN);

        const float sq   = s * s;
        const float norm = s / (sqrtf(sq + EPS) + EPS);
        out[jd] = (sq / (1.0f + sq)) * norm;
    }
}

extern "C" void kernel_launch(void* const* d_in, const int* in_sizes, int n_in,
                              void* d_out, int out_size)
{
    const float* x;
    const float* W;
    if (in_sizes[0] == N_IN * D_IN) {
        x = (const float*)d_in[0];
        W = (const float*)d_in[1];
    } else {
        x = (const float*)d_in[1];
        W = (const float*)d_in[0];
    }
    float* out = (float*)d_out;

    digitcaps_per_jd<<<NJD, NTHR>>>(x, W, out);
}